// round 1
// baseline (speedup 1.0000x reference)
#include <cuda_runtime.h>

#define N_SENS 10000
#define N_HID  400000
#define N_MOT  1000
#define E_SH   4000000
#define E_HH   16000000
#define E_HM   400000

// Scratch (allocation-free rule: __device__ globals)
__device__ float g_sens_spk[N_SENS];
__device__ float g_hid_in[N_HID];
__device__ float g_hid_spk[N_HID];
__device__ float g_mot_in[N_MOT];

// ---------------------------------------------------------------------------
// K1: zero hid accumulator + motor accumulator, compute sensory spikes
// ---------------------------------------------------------------------------
__global__ void k_init(const float* __restrict__ s_in,
                       const float* __restrict__ s_mem) {
    int i = blockIdx.x * blockDim.x + threadIdx.x;
    if (i < N_HID) g_hid_in[i] = 0.0f;
    if (i < N_MOT) g_mot_in[i] = 0.0f;
    if (i < N_SENS) {
        float m = 0.9f * s_mem[i] + 5.0f * s_in[i];
        g_sens_spk[i] = (m > 1.0f) ? 1.0f : 0.0f;
    }
}

// ---------------------------------------------------------------------------
// K2: SH edges (dense sensory spikes ~89%) -> hid_in
// 4 edges / thread via int4/float4
// ---------------------------------------------------------------------------
__global__ void k_sh(const int4* __restrict__ pre,
                     const int4* __restrict__ post,
                     const float4* __restrict__ w) {
    int t = blockIdx.x * blockDim.x + threadIdx.x;
    if (t >= E_SH / 4) return;
    int4 p = pre[t];
    float s0 = g_sens_spk[p.x];
    float s1 = g_sens_spk[p.y];
    float s2 = g_sens_spk[p.z];
    float s3 = g_sens_spk[p.w];
    if (s0 == 0.0f && s1 == 0.0f && s2 == 0.0f && s3 == 0.0f) return;
    int4 q = post[t];
    float4 wv = w[t];
    if (s0 != 0.0f) atomicAdd(&g_hid_in[q.x], wv.x * s0);
    if (s1 != 0.0f) atomicAdd(&g_hid_in[q.y], wv.y * s1);
    if (s2 != 0.0f) atomicAdd(&g_hid_in[q.z], wv.z * s2);
    if (s3 != 0.0f) atomicAdd(&g_hid_in[q.w], wv.w * s3);
}

// ---------------------------------------------------------------------------
// K3: HH edges (~5% dense prev spikes) -> hid_in, scaled by 0.5
// Early-out before loading w/post when all 4 spikes are zero (~81% of threads)
// ---------------------------------------------------------------------------
__global__ void k_hh(const int4* __restrict__ pre,
                     const int4* __restrict__ post,
                     const float4* __restrict__ w,
                     const float* __restrict__ prev_spk) {
    int t = blockIdx.x * blockDim.x + threadIdx.x;
    if (t >= E_HH / 4) return;
    int4 p = pre[t];
    float s0 = prev_spk[p.x];
    float s1 = prev_spk[p.y];
    float s2 = prev_spk[p.z];
    float s3 = prev_spk[p.w];
    if (s0 == 0.0f && s1 == 0.0f && s2 == 0.0f && s3 == 0.0f) return;
    int4 q = post[t];
    float4 wv = w[t];
    if (s0 != 0.0f) atomicAdd(&g_hid_in[q.x], 0.5f * wv.x * s0);
    if (s1 != 0.0f) atomicAdd(&g_hid_in[q.y], 0.5f * wv.y * s1);
    if (s2 != 0.0f) atomicAdd(&g_hid_in[q.z], 0.5f * wv.z * s2);
    if (s3 != 0.0f) atomicAdd(&g_hid_in[q.w], 0.5f * wv.w * s3);
}

// ---------------------------------------------------------------------------
// K4: hidden LIF -> hid_spk
// ---------------------------------------------------------------------------
__global__ void k_hid_spike(const float* __restrict__ h_mem) {
    int i = blockIdx.x * blockDim.x + threadIdx.x;
    if (i >= N_HID) return;
    float m = 0.9f * h_mem[i] + 5.0f * g_hid_in[i];
    g_hid_spk[i] = (m > 1.0f) ? 1.0f : 0.0f;
}

// ---------------------------------------------------------------------------
// K5: HM edges -> mot_in
// ---------------------------------------------------------------------------
__global__ void k_hm(const int4* __restrict__ pre,
                     const int4* __restrict__ post,
                     const float4* __restrict__ w) {
    int t = blockIdx.x * blockDim.x + threadIdx.x;
    if (t >= E_HM / 4) return;
    int4 p = pre[t];
    float s0 = g_hid_spk[p.x];
    float s1 = g_hid_spk[p.y];
    float s2 = g_hid_spk[p.z];
    float s3 = g_hid_spk[p.w];
    if (s0 == 0.0f && s1 == 0.0f && s2 == 0.0f && s3 == 0.0f) return;
    int4 q = post[t];
    float4 wv = w[t];
    if (s0 != 0.0f) atomicAdd(&g_mot_in[q.x], wv.x * s0);
    if (s1 != 0.0f) atomicAdd(&g_mot_in[q.y], wv.y * s1);
    if (s2 != 0.0f) atomicAdd(&g_mot_in[q.z], wv.z * s2);
    if (s3 != 0.0f) atomicAdd(&g_mot_in[q.w], wv.w * s3);
}

// ---------------------------------------------------------------------------
// K6: motor LIF -> output spikes
// ---------------------------------------------------------------------------
__global__ void k_mot(const float* __restrict__ m_mem, float* __restrict__ out) {
    int i = blockIdx.x * blockDim.x + threadIdx.x;
    if (i >= N_MOT) return;
    float m = 0.9f * m_mem[i] + 20.0f * g_mot_in[i];
    out[i] = (m > 1.0f) ? 1.0f : 0.0f;
}

extern "C" void kernel_launch(void* const* d_in, const int* in_sizes, int n_in,
                              void* d_out, int out_size) {
    const float* sensory_input     = (const float*)d_in[0];
    const float* sensory_mem       = (const float*)d_in[1];
    const float* hidden_mem        = (const float*)d_in[2];
    const float* motor_mem         = (const float*)d_in[3];
    const float* hidden_prev_spike = (const float*)d_in[4];
    const float* w_sh              = (const float*)d_in[5];
    const float* w_hh              = (const float*)d_in[6];
    const float* w_hm              = (const float*)d_in[7];
    const int*   sh_pre            = (const int*)d_in[8];
    const int*   sh_post           = (const int*)d_in[9];
    const int*   hh_pre            = (const int*)d_in[10];
    const int*   hh_post           = (const int*)d_in[11];
    const int*   hm_pre            = (const int*)d_in[12];
    const int*   hm_post           = (const int*)d_in[13];
    float* out = (float*)d_out;

    const int T = 256;

    k_init<<<(N_HID + T - 1) / T, T>>>(sensory_input, sensory_mem);

    k_sh<<<(E_SH / 4 + T - 1) / T, T>>>(
        (const int4*)sh_pre, (const int4*)sh_post, (const float4*)w_sh);

    k_hh<<<(E_HH / 4 + T - 1) / T, T>>>(
        (const int4*)hh_pre, (const int4*)hh_post, (const float4*)w_hh,
        hidden_prev_spike);

    k_hid_spike<<<(N_HID + T - 1) / T, T>>>(hidden_mem);

    k_hm<<<(E_HM / 4 + T - 1) / T, T>>>(
        (const int4*)hm_pre, (const int4*)hm_post, (const float4*)w_hm);

    k_mot<<<(N_MOT + T - 1) / T, T>>>(motor_mem, out);
}

// round 2
// speedup vs baseline: 1.1212x; 1.1212x over previous
#include <cuda_runtime.h>
#include <stdint.h>

#define N_SENS 10000
#define N_HID  400000
#define N_MOT  1000
#define E_SH   4000000
#define E_HH   16000000
#define E_HM   400000

#define SENS_WORDS 313      // ceil(10000/32)
#define HID_WORDS  12500    // 400000/32

// Scratch (__device__ globals; allocation-free rule)
__device__ uint32_t g_sens_bits[SENS_WORDS];
__device__ uint32_t g_hid_bits[HID_WORDS];
__device__ float    g_hid_in[N_HID];
__device__ float    g_hid_spk[N_HID];
__device__ float    g_mot_in[N_MOT];

// ---------------------------------------------------------------------------
// K1: zero accumulators, build sensory-spike bitmask + hidden-prev-spike bitmask
// Launched with >= N_HID threads; all warps are full so ballot is safe.
// ---------------------------------------------------------------------------
__global__ void k_init(const float* __restrict__ s_in,
                       const float* __restrict__ s_mem,
                       const float* __restrict__ prev_spk) {
    int i = blockIdx.x * blockDim.x + threadIdx.x;

    // zero hidden accumulator
    if (i < N_HID) g_hid_in[i] = 0.0f;
    if (i < N_MOT) g_mot_in[i] = 0.0f;

    // hidden prev-spike bitmask (N_HID = 12500 full warps)
    {
        int pred = (i < N_HID) ? (prev_spk[i] != 0.0f) : 0;
        uint32_t bits = __ballot_sync(0xFFFFFFFFu, pred);
        if ((i & 31) == 0 && (i >> 5) < HID_WORDS) g_hid_bits[i >> 5] = bits;
    }

    // sensory spike bitmask
    {
        int pred = 0;
        if (i < N_SENS) {
            float m = 0.9f * s_mem[i] + 5.0f * s_in[i];
            pred = (m > 1.0f);
        }
        uint32_t bits = __ballot_sync(0xFFFFFFFFu, pred);
        if ((i & 31) == 0 && (i >> 5) < SENS_WORDS) g_sens_bits[i >> 5] = bits;
    }
}

// ---------------------------------------------------------------------------
// K2: SH edges. Sensory spikes ~89% dense -> always load w/post, bit-test in smem.
// ---------------------------------------------------------------------------
__global__ void __launch_bounds__(256) k_sh(const int4* __restrict__ pre,
                                            const int4* __restrict__ post,
                                            const float4* __restrict__ w) {
    __shared__ uint32_t sb[SENS_WORDS];
    for (int i = threadIdx.x; i < SENS_WORDS; i += blockDim.x)
        sb[i] = g_sens_bits[i];
    __syncthreads();

    const int stride = gridDim.x * blockDim.x;
    for (int t = blockIdx.x * blockDim.x + threadIdx.x; t < E_SH / 4; t += stride) {
        int4 p = pre[t];
        uint32_t b0 = (sb[p.x >> 5] >> (p.x & 31)) & 1u;
        uint32_t b1 = (sb[p.y >> 5] >> (p.y & 31)) & 1u;
        uint32_t b2 = (sb[p.z >> 5] >> (p.z & 31)) & 1u;
        uint32_t b3 = (sb[p.w >> 5] >> (p.w & 31)) & 1u;
        int4 q = post[t];
        float4 wv = w[t];
        if (b0) atomicAdd(&g_hid_in[q.x], wv.x);
        if (b1) atomicAdd(&g_hid_in[q.y], wv.y);
        if (b2) atomicAdd(&g_hid_in[q.z], wv.z);
        if (b3) atomicAdd(&g_hid_in[q.w], wv.w);
    }
}

// ---------------------------------------------------------------------------
// K3: HH edges. Prev spikes ~5% dense. Bitmask (50 KB) in dynamic smem.
// Early-out before touching w/post when all 4 bits are zero (~81%).
// ---------------------------------------------------------------------------
__global__ void __launch_bounds__(512) k_hh(const int4* __restrict__ pre,
                                            const int4* __restrict__ post,
                                            const float4* __restrict__ w) {
    extern __shared__ uint32_t hb[];
    for (int i = threadIdx.x; i < HID_WORDS; i += blockDim.x)
        hb[i] = g_hid_bits[i];
    __syncthreads();

    const int stride = gridDim.x * blockDim.x;
    for (int t = blockIdx.x * blockDim.x + threadIdx.x; t < E_HH / 4; t += stride) {
        int4 p = pre[t];
        uint32_t b0 = (hb[p.x >> 5] >> (p.x & 31)) & 1u;
        uint32_t b1 = (hb[p.y >> 5] >> (p.y & 31)) & 1u;
        uint32_t b2 = (hb[p.z >> 5] >> (p.z & 31)) & 1u;
        uint32_t b3 = (hb[p.w >> 5] >> (p.w & 31)) & 1u;
        if ((b0 | b1 | b2 | b3) == 0u) continue;
        int4 q = post[t];
        float4 wv = w[t];
        if (b0) atomicAdd(&g_hid_in[q.x], 0.5f * wv.x);
        if (b1) atomicAdd(&g_hid_in[q.y], 0.5f * wv.y);
        if (b2) atomicAdd(&g_hid_in[q.z], 0.5f * wv.z);
        if (b3) atomicAdd(&g_hid_in[q.w], 0.5f * wv.w);
    }
}

// ---------------------------------------------------------------------------
// K4: hidden LIF -> hid_spk (float4 vectorized)
// ---------------------------------------------------------------------------
__global__ void k_hid_spike(const float4* __restrict__ h_mem) {
    int i = blockIdx.x * blockDim.x + threadIdx.x;
    if (i >= N_HID / 4) return;
    float4 m = h_mem[i];
    float4 a = reinterpret_cast<const float4*>(g_hid_in)[i];
    float4 s;
    s.x = (0.9f * m.x + 5.0f * a.x > 1.0f) ? 1.0f : 0.0f;
    s.y = (0.9f * m.y + 5.0f * a.y > 1.0f) ? 1.0f : 0.0f;
    s.z = (0.9f * m.z + 5.0f * a.z > 1.0f) ? 1.0f : 0.0f;
    s.w = (0.9f * m.w + 5.0f * a.w > 1.0f) ? 1.0f : 0.0f;
    reinterpret_cast<float4*>(g_hid_spk)[i] = s;
}

// ---------------------------------------------------------------------------
// K5: HM edges -> mot_in (small; plain float gather)
// ---------------------------------------------------------------------------
__global__ void k_hm(const int4* __restrict__ pre,
                     const int4* __restrict__ post,
                     const float4* __restrict__ w) {
    int t = blockIdx.x * blockDim.x + threadIdx.x;
    if (t >= E_HM / 4) return;
    int4 p = pre[t];
    float s0 = g_hid_spk[p.x];
    float s1 = g_hid_spk[p.y];
    float s2 = g_hid_spk[p.z];
    float s3 = g_hid_spk[p.w];
    if (s0 == 0.0f && s1 == 0.0f && s2 == 0.0f && s3 == 0.0f) return;
    int4 q = post[t];
    float4 wv = w[t];
    if (s0 != 0.0f) atomicAdd(&g_mot_in[q.x], wv.x);
    if (s1 != 0.0f) atomicAdd(&g_mot_in[q.y], wv.y);
    if (s2 != 0.0f) atomicAdd(&g_mot_in[q.z], wv.z);
    if (s3 != 0.0f) atomicAdd(&g_mot_in[q.w], wv.w);
}

// ---------------------------------------------------------------------------
// K6: motor LIF -> output
// ---------------------------------------------------------------------------
__global__ void k_mot(const float* __restrict__ m_mem, float* __restrict__ out) {
    int i = blockIdx.x * blockDim.x + threadIdx.x;
    if (i >= N_MOT) return;
    float m = 0.9f * m_mem[i] + 20.0f * g_mot_in[i];
    out[i] = (m > 1.0f) ? 1.0f : 0.0f;
}

extern "C" void kernel_launch(void* const* d_in, const int* in_sizes, int n_in,
                              void* d_out, int out_size) {
    const float* sensory_input     = (const float*)d_in[0];
    const float* sensory_mem       = (const float*)d_in[1];
    const float* hidden_mem        = (const float*)d_in[2];
    const float* motor_mem         = (const float*)d_in[3];
    const float* hidden_prev_spike = (const float*)d_in[4];
    const float* w_sh              = (const float*)d_in[5];
    const float* w_hh              = (const float*)d_in[6];
    const float* w_hm              = (const float*)d_in[7];
    const int*   sh_pre            = (const int*)d_in[8];
    const int*   sh_post           = (const int*)d_in[9];
    const int*   hh_pre            = (const int*)d_in[10];
    const int*   hh_post           = (const int*)d_in[11];
    const int*   hm_pre            = (const int*)d_in[12];
    const int*   hm_post           = (const int*)d_in[13];
    float* out = (float*)d_out;

    static bool attr_set = false;
    const int hh_smem = HID_WORDS * sizeof(uint32_t);  // 50000 bytes
    if (!attr_set) {
        cudaFuncSetAttribute(k_hh, cudaFuncAttributeMaxDynamicSharedMemorySize,
                             hh_smem);
        attr_set = true;
    }

    k_init<<<(N_HID + 255) / 256, 256>>>(sensory_input, sensory_mem,
                                         hidden_prev_spike);

    // SH: grid-stride, ~2048 threads/SM
    k_sh<<<148 * 8, 256>>>((const int4*)sh_pre, (const int4*)sh_post,
                           (const float4*)w_sh);

    // HH: 50 KB smem/block -> 4 blocks/SM, 512 threads each
    k_hh<<<148 * 4, 512, hh_smem>>>((const int4*)hh_pre, (const int4*)hh_post,
                                    (const float4*)w_hh);

    k_hid_spike<<<(N_HID / 4 + 255) / 256, 256>>>((const float4*)hidden_mem);

    k_hm<<<(E_HM / 4 + 255) / 256, 256>>>((const int4*)hm_pre,
                                          (const int4*)hm_post,
                                          (const float4*)w_hm);

    k_mot<<<(N_MOT + 255) / 256, 256>>>(motor_mem, out);
}